// round 1
// baseline (speedup 1.0000x reference)
#include <cuda_runtime.h>
#include <math.h>

// ---------------- problem constants ----------------
#define BB 4
#define CC 64
#define HH 256
#define WWF 256
#define WP 128
#define HW 65536          // HH*WWF
#define HWP 32768         // HH*WP
#define C2 128
#define C4 256
#define NHEADS 4
#define DH 16

// ---------------- scratch (device globals; no runtime alloc) ----------------
__device__ float g_t   [BB*CC*HW];     // pointwise output (full res), reused q/k/v
__device__ float g_qs  [BB*CC*HWP];    // squeezed q (pre-softmax)
__device__ float g_ks  [BB*CC*HWP];    // squeezed k (pre-softmax)
__device__ float g_vs  [BB*CC*HWP];    // squeezed v
__device__ float g_kmax[BB*CC];
__device__ float g_ksum[BB*CC];
__device__ float g_ctxp[64*16*256];    // per-chunk ctx partials [chunk][bh][d*16+e]
__device__ float g_ctx [16*256];       // reduced ctx [bh][d*16+e] (unscaled by ksum)
__device__ float g_att [BB*CC*HWP];    // att, squeezed non-anchor layout
__device__ float g_attn[BB*C2*HW];     // conv5x5 output ("attention")
__device__ float g_m1  [BB*C4*HW];
__device__ float g_m2  [BB*C4*HW];
// pre-transposed weights
__device__ float g_w1t [3*4096];       // q1/k1/v1 as [ci][co]
__device__ float g_wrt [25*64*128];    // r_w as [tap][ci][co]
__device__ float g_wm1t[128*256];      // m1_w as [ci][co]
__device__ float g_wm3t[256*128];      // m3_w as [ci][co]

__device__ __forceinline__ float gelu_exact(float x) {
    return 0.5f * x * (1.0f + erff(x * 0.7071067811865476f));
}

// ---------------- weight prep (transpose for coalesced smem loads) ----------------
__global__ void prep_w(const float* __restrict__ q1, const float* __restrict__ k1,
                       const float* __restrict__ v1, const float* __restrict__ rw,
                       const float* __restrict__ m1, const float* __restrict__ m3) {
    int idx = blockIdx.x * 256 + threadIdx.x;   // 0 .. 282623
    if (idx < 4096) {
        int ci = idx >> 6, co = idx & 63;
        g_w1t[idx] = q1[co*64 + ci];
    } else if (idx < 8192) {
        int l = idx - 4096; int ci = l >> 6, co = l & 63;
        g_w1t[idx] = k1[co*64 + ci];
    } else if (idx < 12288) {
        int l = idx - 8192; int ci = l >> 6, co = l & 63;
        g_w1t[idx] = v1[co*64 + ci];
    } else if (idx < 12288 + 204800) {
        int l = idx - 12288;
        int tap = l >> 13; int r2 = l & 8191; int ci = r2 >> 7, co = r2 & 127;
        g_wrt[l] = rw[(co*64 + ci)*25 + tap];
    } else if (idx < 217088 + 32768) {
        int l = idx - 217088; int ci = l >> 8, co = l & 255;
        g_wm1t[l] = m1[co*128 + ci];
    } else if (idx < 249856 + 32768) {
        int l = idx - 249856; int ci = l >> 7, co = l & 127;
        g_wm3t[l] = m3[co*256 + ci];
    }
}

// ---------------- 1x1 conv C->C with optional checkerboard mask ----------------
// block: 64 pixels x 64 co, 256 threads, 4co x 4px per thread.
// maskmode: 0 none, 1 keep anchor ((h+w)&1==1), 2 keep nonanchor ((h+w)&1==0)
__global__ void pw64(const float* __restrict__ in, int wsel,
                     const float* __restrict__ bias, int maskmode) {
    __shared__ float s_w[4096];
    __shared__ float s_in[4096];
    int t = threadIdx.x;
    int n0 = blockIdx.x * 64;
    int b = n0 >> 16;
    int rem0 = n0 & 65535;
    const float* wt = g_w1t + wsel * 4096;
    #pragma unroll
    for (int i = 0; i < 16; i++) s_w[t + i*256] = wt[t + i*256];
    int h = rem0 >> 8;
    int w0 = rem0 & 255;
    #pragma unroll
    for (int i = 0; i < 16; i++) {
        int idx = t + i*256;
        int ci = idx >> 6, px = idx & 63;
        float v = in[((b*CC + ci) << 16) + rem0 + px];
        if (maskmode) {
            int par = (h + w0 + px) & 1;
            if (maskmode == 1 ? (par == 0) : (par == 1)) v = 0.f;
        }
        s_in[ci*64 + px] = v;
    }
    __syncthreads();
    int cg = t & 15, pg = t >> 4;
    float acc[4][4] = {};
    const float4* w4 = reinterpret_cast<const float4*>(s_w);
    const float4* i4 = reinterpret_cast<const float4*>(s_in);
    #pragma unroll 8
    for (int ci = 0; ci < 64; ci++) {
        float4 wv = w4[ci*16 + cg];
        float4 iv = i4[ci*16 + pg];
        float wr[4] = {wv.x, wv.y, wv.z, wv.w};
        float ir[4] = {iv.x, iv.y, iv.z, iv.w};
        #pragma unroll
        for (int a = 0; a < 4; a++)
            #pragma unroll
            for (int j = 0; j < 4; j++)
                acc[a][j] = fmaf(wr[a], ir[j], acc[a][j]);
    }
    #pragma unroll
    for (int a = 0; a < 4; a++) {
        int co = cg*4 + a;
        float bv = __ldg(bias + co);
        float4 o = make_float4(acc[a][0]+bv, acc[a][1]+bv, acc[a][2]+bv, acc[a][3]+bv);
        *reinterpret_cast<float4*>(&g_t[((b*CC + co) << 16) + rem0 + pg*4]) = o;
    }
}

// ---------------- depthwise 3x3 + parity squeeze ----------------
// Computes output ONLY at the needed parity, writing squeezed (b,c,h,wp).
// anchor=1: full col = 2wp + ((h&1)^1) ; anchor=0: full col = 2wp + (h&1)
__global__ void dwsq(const float* __restrict__ w, const float* __restrict__ bias,
                     int dstsel, int anchor) {
    int idx = blockIdx.x * 256 + threadIdx.x;  // B*C*H*WP
    int wp = idx & 127;
    int h  = (idx >> 7) & 255;
    int c  = (idx >> 15) & 63;
    int b  = idx >> 21;
    int wf = 2*wp + ((h & 1) ^ anchor);
    const float* ip = g_t + ((b*CC + c) << 16);
    float wg[9];
    #pragma unroll
    for (int k = 0; k < 9; k++) wg[k] = __ldg(w + c*9 + k);
    float acc = __ldg(bias + c);
    #pragma unroll
    for (int ky = 0; ky < 3; ky++) {
        int hh = h + ky - 1;
        if (hh < 0 || hh >= HH) continue;
        #pragma unroll
        for (int kx = 0; kx < 3; kx++) {
            int ww = wf + kx - 1;
            if (ww < 0 || ww >= WWF) continue;
            acc += wg[ky*3+kx] * __ldg(ip + hh*WWF + ww);
        }
    }
    float* dst = (dstsel == 0) ? g_qs : (dstsel == 1) ? g_ks : g_vs;
    dst[idx] = acc;
}

// ---------------- k softmax statistics (max, sumexp) per (b,c) row ----------------
__global__ void kstat() {
    int row = blockIdx.x;                  // b*CC + c, 256 rows
    const float* p = g_ks + row * HWP;
    int t = threadIdx.x;
    __shared__ float red[256];
    float m = -1e30f;
    for (int i = t; i < HWP; i += 256) m = fmaxf(m, p[i]);
    red[t] = m; __syncthreads();
    for (int s = 128; s > 0; s >>= 1) { if (t < s) red[t] = fmaxf(red[t], red[t+s]); __syncthreads(); }
    float rm = red[0];
    __syncthreads();
    float sum = 0.f;
    for (int i = t; i < HWP; i += 256) sum += __expf(p[i] - rm);
    red[t] = sum; __syncthreads();
    for (int s = 128; s > 0; s >>= 1) { if (t < s) red[t] += red[t+s]; __syncthreads(); }
    if (t == 0) { g_kmax[row] = rm; g_ksum[row] = red[0]; }
}

// ---------------- ctx partials: ctx[d][e] += exp(k[d]-max) * v[e] ----------------
__global__ void ctx_k() {
    int bh = blockIdx.y;                   // 0..15
    int b = bh >> 2, head = bh & 3;
    int c0 = head * DH;
    int nbase = blockIdx.x * 512;
    int t = threadIdx.x;
    int d = t >> 4, e = t & 15;
    __shared__ float sk[16][65], sv[16][65];
    float acc = 0.f;
    for (int tile = 0; tile < 8; tile++) {
        int nb = nbase + tile*64;
        #pragma unroll
        for (int i = 0; i < 4; i++) {
            int idx = t + i*256;
            int dd = idx >> 6, j = idx & 63;
            int row = b*CC + c0 + dd;
            sk[dd][j] = __expf(g_ks[row*HWP + nb + j] - __ldg(&g_kmax[row]));
            sv[dd][j] = g_vs[row*HWP + nb + j];
        }
        __syncthreads();
        #pragma unroll
        for (int j = 0; j < 64; j++) acc += sk[d][j] * sv[e][j];
        __syncthreads();
    }
    g_ctxp[(blockIdx.x*16 + bh)*256 + t] = acc;
}

// deterministic fixed-order reduction over 64 chunks
__global__ void ctx_red() {
    int bh = blockIdx.x;
    int t = threadIdx.x;
    float s = 0.f;
    #pragma unroll
    for (int ch = 0; ch < 64; ch++) s += g_ctxp[(ch*16 + bh)*256 + t];
    g_ctx[bh*256 + t] = s;
}

// ---------------- att = (ctx/ksum)^T * softmax_d(q), squeezed layout ----------------
__global__ void att_k() {
    int bh = blockIdx.y;
    int b = bh >> 2, head = bh & 3;
    int c0 = head * DH;
    int t = threadIdx.x;
    __shared__ float sc[16][17];
    { int d = t >> 4, e = t & 15;
      sc[d][e] = g_ctx[bh*256 + t] / g_ksum[b*CC + c0 + d]; }
    __syncthreads();
    int pid = blockIdx.x * 256 + t;        // 0..32767 within batch plane
    float qv[16];
    float mx = -1e30f;
    #pragma unroll
    for (int d = 0; d < DH; d++) { qv[d] = g_qs[(b*CC + c0 + d)*HWP + pid]; mx = fmaxf(mx, qv[d]); }
    float s = 0.f;
    #pragma unroll
    for (int d = 0; d < DH; d++) { qv[d] = __expf(qv[d] - mx); s += qv[d]; }
    float inv = 1.f / s;
    #pragma unroll
    for (int d = 0; d < DH; d++) qv[d] *= inv;
    #pragma unroll
    for (int e = 0; e < DH; e++) {
        float a = 0.f;
        #pragma unroll
        for (int d = 0; d < DH; d++) a = fmaf(sc[d][e], qv[d], a);
        g_att[(b*CC + c0 + e)*HWP + pid] = a;
    }
}

// ---------------- shared GEMM step: 128co x 64px, K=64 ----------------
__device__ __forceinline__ void gemm_step(const float* s_w, const float* s_in,
                                          int t, float acc[8][4]) {
    int cg = t & 15, pg = t >> 4;
    const float4* w4 = reinterpret_cast<const float4*>(s_w);
    const float4* i4 = reinterpret_cast<const float4*>(s_in);
    #pragma unroll 8
    for (int ci = 0; ci < 64; ci++) {
        float4 wa = w4[ci*32 + cg*2];
        float4 wb = w4[ci*32 + cg*2 + 1];
        float4 iv = i4[ci*16 + pg];
        float wr[8] = {wa.x, wa.y, wa.z, wa.w, wb.x, wb.y, wb.z, wb.w};
        float ir[4] = {iv.x, iv.y, iv.z, iv.w};
        #pragma unroll
        for (int a = 0; a < 8; a++)
            #pragma unroll
            for (int j = 0; j < 4; j++)
                acc[a][j] = fmaf(wr[a], ir[j], acc[a][j]);
    }
}

// ---------------- parity-aware conv5x5 C->2C ----------------
// block: one (b, row h, parity p, half): 64 same-parity pixels x 128 co.
// Only taps with (dy+dx)%2 == p touch nonzero (non-anchor) input; wp = wc>>1.
__global__ void conv5(const float* __restrict__ rb) {
    __shared__ float smem[12288];
    float* s_w  = smem;         // [ci(64)][co(128)]
    float* s_in = smem + 8192;  // [ci(64)][px(64)]
    int bid = blockIdx.x;
    int half = bid & 1;
    int p    = (bid >> 1) & 1;
    int h    = (bid >> 2) & 255;
    int b    = bid >> 10;
    int t = threadIdx.x;
    int wstart = (p ^ (h & 1)) + half * 128;
    const float* attb = g_att + (b*CC) * HWP;
    float acc[8][4] = {};
    for (int dy = 0; dy < 5; dy++) {
        int hr = h + dy - 2;
        if (hr < 0 || hr >= HH) continue;          // uniform per block
        for (int dx = (p ^ (dy & 1)); dx < 5; dx += 2) {
            int tap = dy*5 + dx;
            #pragma unroll
            for (int i = 0; i < 32; i++)
                s_w[t + i*256] = g_wrt[tap*8192 + t + i*256];
            int base = wstart + dx - 2;
            int wpb = base >> 1;                    // arithmetic floor
            #pragma unroll
            for (int i = 0; i < 16; i++) {
                int idx = t + i*256;
                int ci = idx >> 6, j = idx & 63;
                int wp = wpb + j;
                float v = 0.f;
                if (wp >= 0 && wp < WP) v = attb[ci*HWP + hr*WP + wp];
                s_in[ci*64 + j] = v;
            }
            __syncthreads();
            gemm_step(s_w, s_in, t, acc);
            __syncthreads();
        }
    }
    int cg = t & 15, pg = t >> 4;
    #pragma unroll
    for (int a = 0; a < 8; a++) {
        int co = cg*8 + a;
        float bv = __ldg(rb + co);
        float* op = g_attn + ((b*C2 + co)*HH + h)*WWF;
        #pragma unroll
        for (int jj = 0; jj < 4; jj++)
            op[wstart + 2*(pg*4 + jj)] = acc[a][jj] + bv;
    }
}

// ---------------- m1: 1x1 2C->4C + gelu ----------------
__global__ void pw_m1(const float* __restrict__ bias) {
    __shared__ float smem[12288];
    float* s_w  = smem;
    float* s_in = smem + 8192;
    int t = threadIdx.x;
    int n0 = blockIdx.x * 64;
    int cohalf = blockIdx.y;
    int b = n0 >> 16, rem0 = n0 & 65535;
    float acc[8][4] = {};
    for (int cc = 0; cc < 2; cc++) {
        int ci0 = cc*64;
        #pragma unroll
        for (int i = 0; i < 32; i++) {
            int idx = t + i*256; int ci = idx >> 7, co = idx & 127;
            s_w[idx] = g_wm1t[(ci0+ci)*256 + cohalf*128 + co];
        }
        #pragma unroll
        for (int i = 0; i < 16; i++) {
            int idx = t + i*256; int ci = idx >> 6, px = idx & 63;
            s_in[ci*64 + px] = g_attn[(b*C2 + ci0 + ci)*HW + rem0 + px];
        }
        __syncthreads();
        gemm_step(s_w, s_in, t, acc);
        __syncthreads();
    }
    int cg = t & 15, pg = t >> 4;
    #pragma unroll
    for (int a = 0; a < 8; a++) {
        int co = cohalf*128 + cg*8 + a;
        float bv = __ldg(bias + co);
        float4 o;
        o.x = gelu_exact(acc[a][0] + bv);
        o.y = gelu_exact(acc[a][1] + bv);
        o.z = gelu_exact(acc[a][2] + bv);
        o.w = gelu_exact(acc[a][3] + bv);
        *reinterpret_cast<float4*>(&g_m1[(b*C4 + co)*HW + rem0 + pg*4]) = o;
    }
}

// ---------------- m2: depthwise 3x3 on 4C + gelu ----------------
__global__ void dw_m2(const float* __restrict__ w, const float* __restrict__ bias) {
    int idx = blockIdx.x * 256 + threadIdx.x;  // B*C4*HW
    int wq = idx & 255;
    int h  = (idx >> 8) & 255;
    int c  = (idx >> 16) & 255;
    int b  = idx >> 24;
    const float* ip = g_m1 + ((b*C4 + c) << 16);
    float wg[9];
    #pragma unroll
    for (int k = 0; k < 9; k++) wg[k] = __ldg(w + c*9 + k);
    float acc = __ldg(bias + c);
    #pragma unroll
    for (int ky = 0; ky < 3; ky++) {
        int hh = h + ky - 1;
        if (hh < 0 || hh >= HH) continue;
        #pragma unroll
        for (int kx = 0; kx < 3; kx++) {
            int ww = wq + kx - 1;
            if (ww < 0 || ww >= WWF) continue;
            acc += wg[ky*3+kx] * __ldg(ip + hh*WWF + ww);
        }
    }
    g_m2[idx] = gelu_exact(acc);
}

// ---------------- m3: 1x1 4C->2C + residual, writes d_out ----------------
__global__ void pw_m3(const float* __restrict__ bias, float* __restrict__ out) {
    __shared__ float smem[12288];
    float* s_w  = smem;
    float* s_in = smem + 8192;
    int t = threadIdx.x;
    int n0 = blockIdx.x * 64;
    int b = n0 >> 16, rem0 = n0 & 65535;
    float acc[8][4] = {};
    for (int cc = 0; cc < 4; cc++) {
        int ci0 = cc*64;
        #pragma unroll
        for (int i = 0; i < 32; i++) {
            int idx = t + i*256; int ci = idx >> 7, co = idx & 127;
            s_w[idx] = g_wm3t[(ci0+ci)*128 + co];
        }
        #pragma unroll
        for (int i = 0; i < 16; i++) {
            int idx = t + i*256; int ci = idx >> 6, px = idx & 63;
            s_in[ci*64 + px] = g_m2[(b*C4 + ci0 + ci)*HW + rem0 + px];
        }
        __syncthreads();
        gemm_step(s_w, s_in, t, acc);
        __syncthreads();
    }
    int cg = t & 15, pg = t >> 4;
    #pragma unroll
    for (int a = 0; a < 8; a++) {
        int co = cg*8 + a;
        float bv = __ldg(bias + co);
        int off = (b*C2 + co)*HW + rem0 + pg*4;
        float4 r = *reinterpret_cast<const float4*>(&g_attn[off]);
        float4 o;
        o.x = acc[a][0] + bv + r.x;
        o.y = acc[a][1] + bv + r.y;
        o.z = acc[a][2] + bv + r.z;
        o.w = acc[a][3] + bv + r.w;
        *reinterpret_cast<float4*>(&out[off]) = o;
    }
}

// ---------------- launch ----------------
extern "C" void kernel_launch(void* const* d_in, const int* in_sizes, int n_in,
                              void* d_out, int out_size) {
    const float* x1   = (const float*)d_in[0];
    const float* x2   = (const float*)d_in[1];
    const float* q1_w = (const float*)d_in[2];  const float* q1_b = (const float*)d_in[3];
    const float* q2_w = (const float*)d_in[4];  const float* q2_b = (const float*)d_in[5];
    const float* k1_w = (const float*)d_in[6];  const float* k1_b = (const float*)d_in[7];
    const float* k2_w = (const float*)d_in[8];  const float* k2_b = (const float*)d_in[9];
    const float* v1_w = (const float*)d_in[10]; const float* v1_b = (const float*)d_in[11];
    const float* v2_w = (const float*)d_in[12]; const float* v2_b = (const float*)d_in[13];
    const float* r_w  = (const float*)d_in[14]; const float* r_b  = (const float*)d_in[15];
    const float* m1_w = (const float*)d_in[16]; const float* m1_b = (const float*)d_in[17];
    const float* m2_w = (const float*)d_in[18]; const float* m2_b = (const float*)d_in[19];
    const float* m3_w = (const float*)d_in[20]; const float* m3_b = (const float*)d_in[21];
    float* out = (float*)d_out;

    prep_w<<<1104, 256>>>(q1_w, k1_w, v1_w, r_w, m1_w, m3_w);

    // q path: nonanchor-masked x1 -> 1x1 -> dw3x3 @ nonanchor positions (squeezed)
    pw64<<<4096, 256>>>(x1, 0, q1_b, 2);
    dwsq<<<32768, 256>>>(q2_w, q2_b, 0, 0);
    // k path: anchor-masked x1
    pw64<<<4096, 256>>>(x1, 1, k1_b, 1);
    dwsq<<<32768, 256>>>(k2_w, k2_b, 1, 1);
    // v path: x2, squeezed at anchor positions
    pw64<<<4096, 256>>>(x2, 2, v1_b, 0);
    dwsq<<<32768, 256>>>(v2_w, v2_b, 2, 1);

    kstat<<<256, 256>>>();
    ctx_k<<<dim3(64, 16), 256>>>();
    ctx_red<<<16, 256>>>();
    att_k<<<dim3(128, 16), 256>>>();

    conv5<<<4096, 256>>>(r_b);

    pw_m1<<<dim3(4096, 2), 256>>>(m1_b);
    dw_m2<<<262144, 256>>>(m2_w, m2_b);
    pw_m3<<<4096, 256>>>(m3_b, out);
}

// round 2
// speedup vs baseline: 1.6221x; 1.6221x over previous
#include <cuda_runtime.h>
#include <math.h>

// ---------------- problem constants ----------------
#define BB 4
#define CC 64
#define HH 256
#define WWF 256
#define WP 128
#define HW 65536          // HH*WWF
#define HWP 32768         // HH*WP
#define C2 128
#define C4 256
#define NHEADS 4
#define DH 16

// ---------------- scratch (device globals; no runtime alloc) ----------------
__device__ float g_t   [BB*CC*HW];     // pointwise output (full res), reused q/k/v
__device__ float g_qs  [BB*CC*HWP];    // squeezed q (pre-softmax)
__device__ float g_ks  [BB*CC*HWP];    // squeezed k (pre-softmax)
__device__ float g_vs  [BB*CC*HWP];    // squeezed v
__device__ float g_kmax[BB*CC];
__device__ float g_ksum[BB*CC];
__device__ float g_ctxp[64*16*256];    // per-chunk ctx partials
__device__ float g_ctx [16*256];       // reduced ctx
__device__ float g_att [BB*CC*HWP];    // att, squeezed non-anchor layout
__device__ float g_attn[BB*C2*HW];     // conv5x5 output ("attention")
__device__ float g_m1  [BB*C4*HW];
__device__ float g_m2  [BB*C4*HW];
// weights
__device__ float g_w1t [3*4096];       // q1/k1/v1 as [ci][co] (for FFMA pw64)
__device__ float g_wrh [25*128*64];    // r_w  hi [tap][co][ci]
__device__ float g_wrl [25*128*64];    // r_w  lo
__device__ float g_m1h [256*128];      // m1_w hi [co][ci]
__device__ float g_m1l [256*128];
__device__ float g_m3h [128*256];      // m3_w hi [co][ci]
__device__ float g_m3l [128*256];

__device__ __forceinline__ float gelu_exact(float x) {
    return 0.5f * x * (1.0f + erff(x * 0.7071067811865476f));
}
__device__ __forceinline__ unsigned f2tf32(float x) {
    unsigned r; asm("cvt.rna.tf32.f32 %0, %1;" : "=r"(r) : "f"(x)); return r;
}
__device__ __forceinline__ void mma8(float c[4], const unsigned a[4], const unsigned b[2]) {
    asm volatile("mma.sync.aligned.m16n8k8.row.col.f32.tf32.tf32.f32 "
        "{%0,%1,%2,%3}, {%4,%5,%6,%7}, {%8,%9}, {%0,%1,%2,%3};"
        : "+f"(c[0]), "+f"(c[1]), "+f"(c[2]), "+f"(c[3])
        : "r"(a[0]), "r"(a[1]), "r"(a[2]), "r"(a[3]), "r"(b[0]), "r"(b[1]));
}

// smem geometry for tensor GEMM kernels (512 threads, tile 128co x 128px, K=64)
#define SW_LD 68
#define SI_LD 136
#define SWH_OFF 0
#define SWL_OFF 8704
#define SIH_OFF 17408
#define SIL_OFF 26112
#define SMEM_FL 34816          // floats
#define SMEM_BYTES (SMEM_FL*4)

// One K=64 chunk: warp tile 32x32, 4x4 warp grid, 3-pass tf32 split.
__device__ __forceinline__ void mma_chunk(const float* __restrict__ swh,
                                          const float* __restrict__ swl,
                                          const float* __restrict__ sih,
                                          const float* __restrict__ sil,
                                          int lane, int mbase, int nbase, int bofs,
                                          float acc[2][4][4]) {
    int row = lane >> 2, col = lane & 3;
    #pragma unroll
    for (int ks = 0; ks < 8; ks++) {
        int k0 = ks * 8;
        unsigned ah[2][4], al[2][4];
        #pragma unroll
        for (int mt = 0; mt < 2; mt++) {
            int r0 = (mbase + mt*16 + row)*SW_LD + k0 + col;
            ah[mt][0] = __float_as_uint(swh[r0]);
            ah[mt][1] = __float_as_uint(swh[r0 + 8*SW_LD]);
            ah[mt][2] = __float_as_uint(swh[r0 + 4]);
            ah[mt][3] = __float_as_uint(swh[r0 + 8*SW_LD + 4]);
            al[mt][0] = __float_as_uint(swl[r0]);
            al[mt][1] = __float_as_uint(swl[r0 + 8*SW_LD]);
            al[mt][2] = __float_as_uint(swl[r0 + 4]);
            al[mt][3] = __float_as_uint(swl[r0 + 8*SW_LD + 4]);
        }
        unsigned bh[4][2], bl[4][2];
        #pragma unroll
        for (int nt = 0; nt < 4; nt++) {
            int c0i = (k0 + col)*SI_LD + bofs + nbase + nt*8 + row;
            bh[nt][0] = __float_as_uint(sih[c0i]);
            bh[nt][1] = __float_as_uint(sih[c0i + 4*SI_LD]);
            bl[nt][0] = __float_as_uint(sil[c0i]);
            bl[nt][1] = __float_as_uint(sil[c0i + 4*SI_LD]);
        }
        #pragma unroll
        for (int mt = 0; mt < 2; mt++)
            #pragma unroll
            for (int nt = 0; nt < 4; nt++) {
                mma8(acc[mt][nt], ah[mt], bh[nt]);
                mma8(acc[mt][nt], ah[mt], bl[nt]);
                mma8(acc[mt][nt], al[mt], bh[nt]);
            }
    }
}

// ---------------- weight prep: transpose + tf32 hi/lo split ----------------
__global__ void prep_w(const float* __restrict__ q1, const float* __restrict__ k1,
                       const float* __restrict__ v1, const float* __restrict__ rw,
                       const float* __restrict__ m1, const float* __restrict__ m3) {
    int idx = blockIdx.x * 256 + threadIdx.x;   // 0 .. 282623
    if (idx < 4096) {
        int ci = idx >> 6, co = idx & 63;
        g_w1t[idx] = q1[co*64 + ci];
    } else if (idx < 8192) {
        int l = idx - 4096; int ci = l >> 6, co = l & 63;
        g_w1t[idx] = k1[co*64 + ci];
    } else if (idx < 12288) {
        int l = idx - 8192; int ci = l >> 6, co = l & 63;
        g_w1t[idx] = v1[co*64 + ci];
    } else if (idx < 12288 + 204800) {
        int l = idx - 12288;
        int tap = l >> 13; int r2 = l & 8191; int co = r2 >> 6, ci = r2 & 63;
        float v = rw[(co*64 + ci)*25 + tap];
        unsigned hb = f2tf32(v); float hf = __uint_as_float(hb);
        g_wrh[l] = hf; g_wrl[l] = __uint_as_float(f2tf32(v - hf));
    } else if (idx < 217088 + 32768) {
        int l = idx - 217088;
        float v = m1[l];                        // already [co][ci]
        unsigned hb = f2tf32(v); float hf = __uint_as_float(hb);
        g_m1h[l] = hf; g_m1l[l] = __uint_as_float(f2tf32(v - hf));
    } else if (idx < 249856 + 32768) {
        int l = idx - 249856;
        float v = m3[l];
        unsigned hb = f2tf32(v); float hf = __uint_as_float(hb);
        g_m3h[l] = hf; g_m3l[l] = __uint_as_float(f2tf32(v - hf));
    }
}

// ---------------- 1x1 conv C->C with optional checkerboard mask (FFMA) ----------------
__global__ void pw64(const float* __restrict__ in, int wsel,
                     const float* __restrict__ bias, int maskmode) {
    __shared__ float s_w[4096];
    __shared__ float s_in[4096];
    int t = threadIdx.x;
    int n0 = blockIdx.x * 64;
    int b = n0 >> 16;
    int rem0 = n0 & 65535;
    const float* wt = g_w1t + wsel * 4096;
    #pragma unroll
    for (int i = 0; i < 16; i++) s_w[t + i*256] = wt[t + i*256];
    int h = rem0 >> 8;
    int w0 = rem0 & 255;
    #pragma unroll
    for (int i = 0; i < 16; i++) {
        int idx = t + i*256;
        int ci = idx >> 6, px = idx & 63;
        float v = in[((b*CC + ci) << 16) + rem0 + px];
        if (maskmode) {
            int par = (h + w0 + px) & 1;
            if (maskmode == 1 ? (par == 0) : (par == 1)) v = 0.f;
        }
        s_in[ci*64 + px] = v;
    }
    __syncthreads();
    int cg = t & 15, pg = t >> 4;
    float acc[4][4] = {};
    const float4* w4 = reinterpret_cast<const float4*>(s_w);
    const float4* i4 = reinterpret_cast<const float4*>(s_in);
    #pragma unroll 8
    for (int ci = 0; ci < 64; ci++) {
        float4 wv = w4[ci*16 + cg];
        float4 iv = i4[ci*16 + pg];
        float wr[4] = {wv.x, wv.y, wv.z, wv.w};
        float ir[4] = {iv.x, iv.y, iv.z, iv.w};
        #pragma unroll
        for (int a = 0; a < 4; a++)
            #pragma unroll
            for (int j = 0; j < 4; j++)
                acc[a][j] = fmaf(wr[a], ir[j], acc[a][j]);
    }
    #pragma unroll
    for (int a = 0; a < 4; a++) {
        int co = cg*4 + a;
        float bv = __ldg(bias + co);
        float4 o = make_float4(acc[a][0]+bv, acc[a][1]+bv, acc[a][2]+bv, acc[a][3]+bv);
        *reinterpret_cast<float4*>(&g_t[((b*CC + co) << 16) + rem0 + pg*4]) = o;
    }
}

// ---------------- depthwise 3x3 + parity squeeze ----------------
__global__ void dwsq(const float* __restrict__ w, const float* __restrict__ bias,
                     int dstsel, int anchor) {
    int idx = blockIdx.x * 256 + threadIdx.x;  // B*C*H*WP
    int wp = idx & 127;
    int h  = (idx >> 7) & 255;
    int c  = (idx >> 15) & 63;
    int b  = idx >> 21;
    int wf = 2*wp + ((h & 1) ^ anchor);
    const float* ip = g_t + ((b*CC + c) << 16);
    float wg[9];
    #pragma unroll
    for (int k = 0; k < 9; k++) wg[k] = __ldg(w + c*9 + k);
    float acc = __ldg(bias + c);
    #pragma unroll
    for (int ky = 0; ky < 3; ky++) {
        int hh = h + ky - 1;
        if (hh < 0 || hh >= HH) continue;
        #pragma unroll
        for (int kx = 0; kx < 3; kx++) {
            int ww = wf + kx - 1;
            if (ww < 0 || ww >= WWF) continue;
            acc += wg[ky*3+kx] * __ldg(ip + hh*WWF + ww);
        }
    }
    float* dst = (dstsel == 0) ? g_qs : (dstsel == 1) ? g_ks : g_vs;
    dst[idx] = acc;
}

// ---------------- k softmax statistics ----------------
__global__ void kstat() {
    int row = blockIdx.x;
    const float* p = g_ks + row * HWP;
    int t = threadIdx.x;
    __shared__ float red[256];
    float m = -1e30f;
    for (int i = t; i < HWP; i += 256) m = fmaxf(m, p[i]);
    red[t] = m; __syncthreads();
    for (int s = 128; s > 0; s >>= 1) { if (t < s) red[t] = fmaxf(red[t], red[t+s]); __syncthreads(); }
    float rm = red[0];
    __syncthreads();
    float sum = 0.f;
    for (int i = t; i < HWP; i += 256) sum += __expf(p[i] - rm);
    red[t] = sum; __syncthreads();
    for (int s = 128; s > 0; s >>= 1) { if (t < s) red[t] += red[t+s]; __syncthreads(); }
    if (t == 0) { g_kmax[row] = rm; g_ksum[row] = red[0]; }
}

// ---------------- ctx partials ----------------
__global__ void ctx_k() {
    int bh = blockIdx.y;
    int b = bh >> 2, head = bh & 3;
    int c0 = head * DH;
    int nbase = blockIdx.x * 512;
    int t = threadIdx.x;
    int d = t >> 4, e = t & 15;
    __shared__ float sk[16][65], sv[16][65];
    float acc = 0.f;
    for (int tile = 0; tile < 8; tile++) {
        int nb = nbase + tile*64;
        #pragma unroll
        for (int i = 0; i < 4; i++) {
            int idx = t + i*256;
            int dd = idx >> 6, j = idx & 63;
            int row = b*CC + c0 + dd;
            sk[dd][j] = __expf(g_ks[row*HWP + nb + j] - __ldg(&g_kmax[row]));
            sv[dd][j] = g_vs[row*HWP + nb + j];
        }
        __syncthreads();
        #pragma unroll
        for (int j = 0; j < 64; j++) acc += sk[d][j] * sv[e][j];
        __syncthreads();
    }
    g_ctxp[(blockIdx.x*16 + bh)*256 + t] = acc;
}

__global__ void ctx_red() {
    int bh = blockIdx.x;
    int t = threadIdx.x;
    float s = 0.f;
    #pragma unroll
    for (int ch = 0; ch < 64; ch++) s += g_ctxp[(ch*16 + bh)*256 + t];
    g_ctx[bh*256 + t] = s;
}

// ---------------- att = (ctx/ksum)^T * softmax_d(q) ----------------
__global__ void att_k() {
    int bh = blockIdx.y;
    int b = bh >> 2, head = bh & 3;
    int c0 = head * DH;
    int t = threadIdx.x;
    __shared__ float sc[16][17];
    { int d = t >> 4, e = t & 15;
      sc[d][e] = g_ctx[bh*256 + t] / g_ksum[b*CC + c0 + d]; }
    __syncthreads();
    int pid = blockIdx.x * 256 + t;
    float qv[16];
    float mx = -1e30f;
    #pragma unroll
    for (int d = 0; d < DH; d++) { qv[d] = g_qs[(b*CC + c0 + d)*HWP + pid]; mx = fmaxf(mx, qv[d]); }
    float s = 0.f;
    #pragma unroll
    for (int d = 0; d < DH; d++) { qv[d] = __expf(qv[d] - mx); s += qv[d]; }
    float inv = 1.f / s;
    #pragma unroll
    for (int d = 0; d < DH; d++) qv[d] *= inv;
    #pragma unroll
    for (int e = 0; e < DH; e++) {
        float a = 0.f;
        #pragma unroll
        for (int d = 0; d < DH; d++) a = fmaf(sc[d][e], qv[d], a);
        g_att[(b*CC + c0 + e)*HWP + pid] = a;
    }
}

// ---------------- parity-aware conv5x5 C->2C (tensor) ----------------
// block: (b, row h, parity p): 128 same-parity pixels x 128 co. 512 threads.
__global__ __launch_bounds__(512, 1) void conv5t(const float* __restrict__ rb) {
    extern __shared__ float smem[];
    float* swh = smem + SWH_OFF;
    float* swl = smem + SWL_OFF;
    float* sih = smem + SIH_OFF;
    float* sil = smem + SIL_OFF;
    int bid = blockIdx.x;
    int p = bid & 1, h = (bid >> 1) & 255, b = bid >> 9;
    int t = threadIdx.x, lane = t & 31, warp = t >> 5;
    int mbase = (warp & 3) * 32, nbase = (warp >> 2) * 32;
    int wstart = p ^ (h & 1);
    const float* attb = g_att + b*CC*HWP;
    float acc[2][4][4] = {};
    for (int dy = 0; dy < 5; dy++) {
        int hr = h + dy - 2;
        if (hr < 0 || hr >= HH) continue;
        int dx0 = p ^ (dy & 1);
        int wpb0 = (wstart + dx0 - 2) >> 1;
        __syncthreads();                       // prior tap done reading s_in
        #pragma unroll
        for (int i = 0; i < 17; i++) {
            int idx = t + i*512;
            if (idx < 8320) {
                int ci = idx / 130, c = idx - ci*130;
                int wp = wpb0 + c;
                float v = (wp >= 0 && wp < WP) ? attb[ci*HWP + hr*WP + wp] : 0.f;
                unsigned hb = f2tf32(v); float hf = __uint_as_float(hb);
                sih[ci*SI_LD + c] = hf;
                sil[ci*SI_LD + c] = __uint_as_float(f2tf32(v - hf));
            }
        }
        for (int dx = dx0; dx < 5; dx += 2) {
            int tap = dy*5 + dx;
            __syncthreads();                   // prior gemm done reading s_w
            #pragma unroll
            for (int i = 0; i < 16; i++) {
                int idx = t + i*512;
                int co = idx >> 6, ci = idx & 63;
                swh[co*SW_LD + ci] = g_wrh[tap*8192 + idx];
                swl[co*SW_LD + ci] = g_wrl[tap*8192 + idx];
            }
            __syncthreads();
            mma_chunk(swh, swl, sih, sil, lane, mbase, nbase, (dx - dx0) >> 1, acc);
        }
    }
    // epilogue: standard layout, stride-2 columns
    int row = lane >> 2, col = lane & 3;
    #pragma unroll
    for (int mt = 0; mt < 2; mt++) {
        #pragma unroll
        for (int nt = 0; nt < 4; nt++) {
            int co0 = mbase + mt*16 + row;
            int px0 = nbase + nt*8 + col*2;
            int wc0 = wstart + 2*px0;
            float bv0 = __ldg(rb + co0), bv8 = __ldg(rb + co0 + 8);
            float* r0p = g_attn + ((size_t)(b*C2 + co0)*HH + h)*WWF;
            float* r8p = r0p + (size_t)8*HH*WWF;
            r0p[wc0]     = acc[mt][nt][0] + bv0;
            r0p[wc0 + 2] = acc[mt][nt][1] + bv0;
            r8p[wc0]     = acc[mt][nt][2] + bv8;
            r8p[wc0 + 2] = acc[mt][nt][3] + bv8;
        }
    }
}

// ---------------- m1: 1x1 2C->4C + gelu (tensor) ----------------
__global__ __launch_bounds__(512, 1) void pw_m1t(const float* __restrict__ bias) {
    extern __shared__ float smem[];
    float* swh = smem + SWH_OFF;
    float* swl = smem + SWL_OFF;
    float* sih = smem + SIH_OFF;
    float* sil = smem + SIL_OFF;
    int t = threadIdx.x, lane = t & 31, warp = t >> 5;
    int mbase = (warp & 3) * 32, nbase = (warp >> 2) * 32;
    int n0 = blockIdx.x * 128;
    int cohalf = blockIdx.y;
    int b = n0 >> 16, rem0 = n0 & 65535;
    float acc[2][4][4] = {};
    for (int cc = 0; cc < 2; cc++) {
        int ci0 = cc * 64;
        if (cc) __syncthreads();
        #pragma unroll
        for (int i = 0; i < 16; i++) {
            int idx = t + i*512;
            int co = idx >> 6, ci = idx & 63;
            swh[co*SW_LD + ci] = g_m1h[(cohalf*128 + co)*128 + ci0 + ci];
            swl[co*SW_LD + ci] = g_m1l[(cohalf*128 + co)*128 + ci0 + ci];
        }
        #pragma unroll
        for (int i = 0; i < 16; i++) {
            int idx = t + i*512;
            int ci = idx >> 7, px = idx & 127;
            float v = g_attn[(size_t)(b*C2 + ci0 + ci)*HW + rem0 + px];
            unsigned hb = f2tf32(v); float hf = __uint_as_float(hb);
            sih[ci*SI_LD + px] = hf;
            sil[ci*SI_LD + px] = __uint_as_float(f2tf32(v - hf));
        }
        __syncthreads();
        mma_chunk(swh, swl, sih, sil, lane, mbase, nbase, 0, acc);
    }
    int row = lane >> 2, col = lane & 3;
    #pragma unroll
    for (int mt = 0; mt < 2; mt++) {
        #pragma unroll
        for (int nt = 0; nt < 4; nt++) {
            int co = cohalf*128 + mbase + mt*16 + row;
            int px = nbase + nt*8 + col*2;
            float bv0 = __ldg(bias + co), bv8 = __ldg(bias + co + 8);
            float2 o0 = make_float2(gelu_exact(acc[mt][nt][0] + bv0),
                                    gelu_exact(acc[mt][nt][1] + bv0));
            float2 o8 = make_float2(gelu_exact(acc[mt][nt][2] + bv8),
                                    gelu_exact(acc[mt][nt][3] + bv8));
            *reinterpret_cast<float2*>(&g_m1[(size_t)(b*C4 + co)*HW + rem0 + px]) = o0;
            *reinterpret_cast<float2*>(&g_m1[(size_t)(b*C4 + co + 8)*HW + rem0 + px]) = o8;
        }
    }
}

// ---------------- m2: depthwise 3x3 on 4C + gelu ----------------
__global__ void dw_m2(const float* __restrict__ w, const float* __restrict__ bias) {
    int idx = blockIdx.x * 256 + threadIdx.x;
    int wq = idx & 255;
    int h  = (idx >> 8) & 255;
    int c  = (idx >> 16) & 255;
    int b  = idx >> 24;
    const float* ip = g_m1 + ((size_t)(b*C4 + c) << 16);
    float wg[9];
    #pragma unroll
    for (int k = 0; k < 9; k++) wg[k] = __ldg(w + c*9 + k);
    float acc = __ldg(bias + c);
    #pragma unroll
    for (int ky = 0; ky < 3; ky++) {
        int hh = h + ky - 1;
        if (hh < 0 || hh >= HH) continue;
        #pragma unroll
        for (int kx = 0; kx < 3; kx++) {
            int ww = wq + kx - 1;
            if (ww < 0 || ww >= WWF) continue;
            acc += wg[ky*3+kx] * __ldg(ip + hh*WWF + ww);
        }
    }
    g_m2[idx] = gelu_exact(acc);
}

// ---------------- m3: 1x1 4C->2C + residual (tensor), writes d_out ----------------
__global__ __launch_bounds__(512, 1) void pw_m3t(const float* __restrict__ bias,
                                                 float* __restrict__ out) {
    extern __shared__ float smem[];
    float* swh = smem + SWH_OFF;
    float* swl = smem + SWL_OFF;
    float* sih = smem + SIH_OFF;
    float* sil = smem + SIL_OFF;
    int t = threadIdx.x, lane = t & 31, warp = t >> 5;
    int mbase = (warp & 3) * 32, nbase = (warp >> 2) * 32;
    int n0 = blockIdx.x * 128;
    int b = n0 >> 16, rem0 = n0 & 65535;
    float acc[2][4][4] = {};
    for (int cc = 0; cc < 4; cc++) {
        int ci0 = cc * 64;
        if (cc) __syncthreads();
        #pragma unroll
        for (int i = 0; i < 16; i++) {
            int idx = t + i*512;
            int co = idx >> 6, ci = idx & 63;
            swh[co*SW_LD + ci] = g_m3h[co*256 + ci0 + ci];
            swl[co*SW_LD + ci] = g_m3l[co*256 + ci0 + ci];
        }
        #pragma unroll
        for (int i = 0; i < 16; i++) {
            int idx = t + i*512;
            int ci = idx >> 7, px = idx & 127;
            float v = g_m2[(size_t)(b*C4 + ci0 + ci)*HW + rem0 + px];
            unsigned hb = f2tf32(v); float hf = __uint_as_float(hb);
            sih[ci*SI_LD + px] = hf;
            sil[ci*SI_LD + px] = __uint_as_float(f2tf32(v - hf));
        }
        __syncthreads();
        mma_chunk(swh, swl, sih, sil, lane, mbase, nbase, 0, acc);
    }
    int row = lane >> 2, col = lane & 3;
    #pragma unroll
    for (int mt = 0; mt < 2; mt++) {
        #pragma unroll
        for (int nt = 0; nt < 4; nt++) {
            int co = mbase + mt*16 + row;
            int px = nbase + nt*8 + col*2;
            float bv0 = __ldg(bias + co), bv8 = __ldg(bias + co + 8);
            size_t off0 = (size_t)(b*C2 + co)*HW + rem0 + px;
            size_t off8 = (size_t)(b*C2 + co + 8)*HW + rem0 + px;
            float2 r0 = *reinterpret_cast<const float2*>(&g_attn[off0]);
            float2 r8 = *reinterpret_cast<const float2*>(&g_attn[off8]);
            float2 o0 = make_float2(acc[mt][nt][0] + bv0 + r0.x,
                                    acc[mt][nt][1] + bv0 + r0.y);
            float2 o8 = make_float2(acc[mt][nt][2] + bv8 + r8.x,
                                    acc[mt][nt][3] + bv8 + r8.y);
            *reinterpret_cast<float2*>(&out[off0]) = o0;
            *reinterpret_cast<float2*>(&out[off8]) = o8;
        }
    }
}

// ---------------- launch ----------------
extern "C" void kernel_launch(void* const* d_in, const int* in_sizes, int n_in,
                              void* d_out, int out_size) {
    const float* x1   = (const float*)d_in[0];
    const float* x2   = (const float*)d_in[1];
    const float* q1_w = (const float*)d_in[2];  const float* q1_b = (const float*)d_in[3];
    const float* q2_w = (const float*)d_in[4];  const float* q2_b = (const float*)d_in[5];
    const float* k1_w = (const float*)d_in[6];  const float* k1_b = (const float*)d_in[7];
    const float* k2_w = (const float*)d_in[8];  const float* k2_b = (const float*)d_in[9];
    const float* v1_w = (const float*)d_in[10]; const float* v1_b = (const float*)d_in[11];
    const float* v2_w = (const float*)d_in[12]; const float* v2_b = (const float*)d_in[13];
    const float* r_w  = (const float*)d_in[14]; const float* r_b  = (const float*)d_in[15];
    const float* m1_w = (const float*)d_in[16]; const float* m1_b = (const float*)d_in[17];
    const float* m2_w = (const float*)d_in[18]; const float* m2_b = (const float*)d_in[19];
    const float* m3_w = (const float*)d_in[20]; const float* m3_b = (const float*)d_in[21];
    float* out = (float*)d_out;

    cudaFuncSetAttribute(conv5t, cudaFuncAttributeMaxDynamicSharedMemorySize, SMEM_BYTES);
    cudaFuncSetAttribute(pw_m1t, cudaFuncAttributeMaxDynamicSharedMemorySize, SMEM_BYTES);
    cudaFuncSetAttribute(pw_m3t, cudaFuncAttributeMaxDynamicSharedMemorySize, SMEM_BYTES);

    prep_w<<<1104, 256>>>(q1_w, k1_w, v1_w, r_w, m1_w, m3_w);

    pw64<<<4096, 256>>>(x1, 0, q1_b, 2);
    dwsq<<<32768, 256>>>(q2_w, q2_b, 0, 0);
    pw64<<<4096, 256>>>(x1, 1, k1_b, 1);
    dwsq<<<32768, 256>>>(k2_w, k2_b, 1, 1);
    pw64<<<4096, 256>>>(x2, 2, v1_b, 0);
    dwsq<<<32768, 256>>>(v2_w, v2_b, 2, 1);

    kstat<<<256, 256>>>();
    ctx_k<<<dim3(64, 16), 256>>>();
    ctx_red<<<16, 256>>>();
    att_k<<<dim3(128, 16), 256>>>();

    conv5t<<<2048, 512, SMEM_BYTES>>>(r_b);

    pw_m1t<<<dim3(2048, 2), 512, SMEM_BYTES>>>(m1_b);
    dw_m2<<<262144, 256>>>(m2_w, m2_b);
    pw_m3t<<<2048, 512, SMEM_BYTES>>>(m3_b, out);
}

// round 7
// speedup vs baseline: 2.2128x; 1.3641x over previous
#include <cuda_runtime.h>
#include <cuda_bf16.h>
#include <math.h>

// ---------------- problem constants ----------------
#define BB 4
#define CC 64
#define HH 256
#define WWF 256
#define WP 128
#define HW 65536          // HH*WWF
#define HWP 32768         // HH*WP
#define C2 128
#define C4 256
#define NHEADS 4
#define DH 16

// ---------------- scratch (device globals; no runtime alloc) ----------------
__device__ float g_t   [BB*CC*HW];     // pointwise output (full res), reused q/k/v
__device__ float g_qs  [BB*CC*HWP];    // squeezed q (pre-softmax)
__device__ float g_ks  [BB*CC*HWP];    // squeezed k (pre-softmax)
__device__ float g_vs  [BB*CC*HWP];    // squeezed v
__device__ float g_kmax[BB*CC];
__device__ float g_ksum[BB*CC];
__device__ float g_ctxp[64*16*256];
__device__ float g_ctx [16*256];
__device__ float g_att [BB*CC*HWP];    // att, squeezed non-anchor layout
__device__ float g_attn[BB*C2*HW];     // conv5x5 output ("attention")
__device__ float g_m1  [BB*C4*HW];
__device__ float g_m2  [BB*C4*HW];
// weights
__device__ float g_w1t [3*4096];       // q1/k1/v1 as [ci][co] (FFMA pointwise)
__device__ unsigned g_wrhu[25*4096];   // r_w hi bf16x2 [tap][co(128)][cipair(32)]
__device__ unsigned g_wrlu[25*4096];
__device__ unsigned g_m1hu[256*64];    // m1_w [co(256)][cipair(64)]
__device__ unsigned g_m1lu[256*64];
__device__ unsigned g_m3hu[128*128];   // m3_w [co(128)][cipair(128)]
__device__ unsigned g_m3lu[128*128];

__device__ __forceinline__ float gelu_exact(float x) {
    return 0.5f * x * (1.0f + erff(x * 0.7071067811865476f));
}
__device__ __forceinline__ unsigned pack2(float a, float b) {
    __nv_bfloat162 p = __floats2bfloat162_rn(a, b);
    return *reinterpret_cast<unsigned*>(&p);
}
__device__ __forceinline__ void mma16(float c[4], const unsigned a[4], const unsigned b[2]) {
    asm volatile("mma.sync.aligned.m16n8k16.row.col.f32.bf16.bf16.f32 "
        "{%0,%1,%2,%3}, {%4,%5,%6,%7}, {%8,%9}, {%0,%1,%2,%3};"
        : "+f"(c[0]), "+f"(c[1]), "+f"(c[2]), "+f"(c[3])
        : "r"(a[0]), "r"(a[1]), "r"(a[2]), "r"(a[3]), "r"(b[0]), "r"(b[1]));
}

// smem geometry (uint units). A: [co(128)][kpair(32)] pad->36 ; B: [kpair(32)][px] pad->136
#define A_LD 36
#define B_LD 136
#define SWH_U 0
#define SWL_U 4608
#define SIH_U 9216
#define SIL_U 13568
#define SMEM_U 17920
#define SMEM_BYTES (SMEM_U*4)

// One K=64 chunk: tile 128co x 128px, 4x4 warps of 32x32, 3-pass bf16 split.
__device__ __forceinline__ void mma_chunk(const unsigned* __restrict__ swh,
                                          const unsigned* __restrict__ swl,
                                          const unsigned* __restrict__ sih,
                                          const unsigned* __restrict__ sil,
                                          int lane, int mbase, int nbase, int bofs,
                                          float acc[2][4][4]) {
    int r = lane >> 2, c = lane & 3;
    #pragma unroll
    for (int ks = 0; ks < 4; ks++) {
        int k0c = ks * 8;
        unsigned ah[2][4], al[2][4];
        #pragma unroll
        for (int mt = 0; mt < 2; mt++) {
            int base = (mbase + mt*16 + r)*A_LD + k0c + c;
            ah[mt][0] = swh[base];
            ah[mt][1] = swh[base + 8*A_LD];
            ah[mt][2] = swh[base + 4];
            ah[mt][3] = swh[base + 8*A_LD + 4];
            al[mt][0] = swl[base];
            al[mt][1] = swl[base + 8*A_LD];
            al[mt][2] = swl[base + 4];
            al[mt][3] = swl[base + 8*A_LD + 4];
        }
        unsigned bh[4][2], bl[4][2];
        #pragma unroll
        for (int nt = 0; nt < 4; nt++) {
            int n = bofs + nbase + nt*8 + r;
            bh[nt][0] = sih[(k0c + c)*B_LD + n];
            bh[nt][1] = sih[(k0c + c + 4)*B_LD + n];
            bl[nt][0] = sil[(k0c + c)*B_LD + n];
            bl[nt][1] = sil[(k0c + c + 4)*B_LD + n];
        }
        #pragma unroll
        for (int mt = 0; mt < 2; mt++)
            #pragma unroll
            for (int nt = 0; nt < 4; nt++) {
                mma16(acc[mt][nt], ah[mt], bh[nt]);
                mma16(acc[mt][nt], ah[mt], bl[nt]);
                mma16(acc[mt][nt], al[mt], bh[nt]);
            }
    }
}

// ---------------- weight prep ----------------
__global__ void prep_w(const float* __restrict__ q1, const float* __restrict__ k1,
                       const float* __restrict__ v1, const float* __restrict__ rw,
                       const float* __restrict__ m1, const float* __restrict__ m3) {
    int idx = blockIdx.x * 256 + threadIdx.x;   // 0 .. 147455
    if (idx < 4096) {
        int ci = idx >> 6, co = idx & 63;
        g_w1t[idx] = q1[co*64 + ci];
    } else if (idx < 8192) {
        int l = idx - 4096; int ci = l >> 6, co = l & 63;
        g_w1t[idx] = k1[co*64 + ci];
    } else if (idx < 12288) {
        int l = idx - 8192; int ci = l >> 6, co = l & 63;
        g_w1t[idx] = v1[co*64 + ci];
    } else if (idx < 12288 + 102400) {
        int l = idx - 12288;
        int tap = l >> 12; int rr = l & 4095; int co = rr >> 5, kc = rr & 31;
        float v0 = rw[(co*64 + 2*kc  )*25 + tap];
        float v1v= rw[(co*64 + 2*kc+1)*25 + tap];
        float h0 = __bfloat162float(__float2bfloat16_rn(v0));
        float h1 = __bfloat162float(__float2bfloat16_rn(v1v));
        g_wrhu[l] = pack2(h0, h1);
        g_wrlu[l] = pack2(v0 - h0, v1v - h1);
    } else if (idx < 114688 + 16384) {
        int l = idx - 114688; int co = l >> 6, kc = l & 63;
        float v0 = m1[co*128 + 2*kc], v1v = m1[co*128 + 2*kc+1];
        float h0 = __bfloat162float(__float2bfloat16_rn(v0));
        float h1 = __bfloat162float(__float2bfloat16_rn(v1v));
        g_m1hu[l] = pack2(h0, h1);
        g_m1lu[l] = pack2(v0 - h0, v1v - h1);
    } else if (idx < 131072 + 16384) {
        int l = idx - 131072; int co = l >> 7, kc = l & 127;
        float v0 = m3[co*256 + 2*kc], v1v = m3[co*256 + 2*kc+1];
        float h0 = __bfloat162float(__float2bfloat16_rn(v0));
        float h1 = __bfloat162float(__float2bfloat16_rn(v1v));
        g_m3hu[l] = pack2(h0, h1);
        g_m3lu[l] = pack2(v0 - h0, v1v - h1);
    }
}

// ---------------- 1x1 conv C->C with optional checkerboard mask (round-2 exact) ----------------
// maskmode: 0 none, 1 keep anchor ((h+w)&1==1), 2 keep nonanchor ((h+w)&1==0)
__global__ void pw64(const float* __restrict__ in, int wsel,
                     const float* __restrict__ bias, int maskmode) {
    __shared__ float s_w[4096];
    __shared__ float s_in[4096];
    int t = threadIdx.x;
    int n0 = blockIdx.x * 64;
    int b = n0 >> 16;
    int rem0 = n0 & 65535;
    const float* wt = g_w1t + wsel * 4096;
    #pragma unroll
    for (int i = 0; i < 16; i++) s_w[t + i*256] = wt[t + i*256];
    int h = rem0 >> 8;
    int w0 = rem0 & 255;
    #pragma unroll
    for (int i = 0; i < 16; i++) {
        int idx = t + i*256;
        int ci = idx >> 6, px = idx & 63;
        float v = in[((b*CC + ci) << 16) + rem0 + px];
        if (maskmode) {
            int par = (h + w0 + px) & 1;
            if (maskmode == 1 ? (par == 0) : (par == 1)) v = 0.f;
        }
        s_in[ci*64 + px] = v;
    }
    __syncthreads();
    int cg = t & 15, pg = t >> 4;
    float acc[4][4] = {};
    const float4* w4 = reinterpret_cast<const float4*>(s_w);
    const float4* i4 = reinterpret_cast<const float4*>(s_in);
    #pragma unroll 8
    for (int ci = 0; ci < 64; ci++) {
        float4 wv = w4[ci*16 + cg];
        float4 iv = i4[ci*16 + pg];
        float wr[4] = {wv.x, wv.y, wv.z, wv.w};
        float ir[4] = {iv.x, iv.y, iv.z, iv.w};
        #pragma unroll
        for (int a = 0; a < 4; a++)
            #pragma unroll
            for (int j = 0; j < 4; j++)
                acc[a][j] = fmaf(wr[a], ir[j], acc[a][j]);
    }
    #pragma unroll
    for (int a = 0; a < 4; a++) {
        int co = cg*4 + a;
        float bv = __ldg(bias + co);
        float4 o = make_float4(acc[a][0]+bv, acc[a][1]+bv, acc[a][2]+bv, acc[a][3]+bv);
        *reinterpret_cast<float4*>(&g_t[((b*CC + co) << 16) + rem0 + pg*4]) = o;
    }
}

// ---------------- depthwise 3x3 + parity squeeze (round-2 exact) ----------------
__global__ void dwsq(const float* __restrict__ w, const float* __restrict__ bias,
                     int dstsel, int anchor) {
    int idx = blockIdx.x * 256 + threadIdx.x;  // B*C*H*WP
    int wp = idx & 127;
    int h  = (idx >> 7) & 255;
    int c  = (idx >> 15) & 63;
    int b  = idx >> 21;
    int wf = 2*wp + ((h & 1) ^ anchor);
    const float* ip = g_t + ((b*CC + c) << 16);
    float wg[9];
    #pragma unroll
    for (int k = 0; k < 9; k++) wg[k] = __ldg(w + c*9 + k);
    float acc = __ldg(bias + c);
    #pragma unroll
    for (int ky = 0; ky < 3; ky++) {
        int hh = h + ky - 1;
        if (hh < 0 || hh >= HH) continue;
        #pragma unroll
        for (int kx = 0; kx < 3; kx++) {
            int ww = wf + kx - 1;
            if (ww < 0 || ww >= WWF) continue;
            acc += wg[ky*3+kx] * __ldg(ip + hh*WWF + ww);
        }
    }
    float* dst = (dstsel == 0) ? g_qs : (dstsel == 1) ? g_ks : g_vs;
    dst[idx] = acc;
}

// ---------------- k softmax statistics ----------------
__global__ void kstat() {
    int row = blockIdx.x;
    const float* p = g_ks + row * HWP;
    int t = threadIdx.x;
    __shared__ float red[256];
    float m = -1e30f;
    for (int i = t; i < HWP; i += 256) m = fmaxf(m, p[i]);
    red[t] = m; __syncthreads();
    for (int s = 128; s > 0; s >>= 1) { if (t < s) red[t] = fmaxf(red[t], red[t+s]); __syncthreads(); }
    float rm = red[0];
    __syncthreads();
    float sum = 0.f;
    for (int i = t; i < HWP; i += 256) sum += __expf(p[i] - rm);
    red[t] = sum; __syncthreads();
    for (int s = 128; s > 0; s >>= 1) { if (t < s) red[t] += red[t+s]; __syncthreads(); }
    if (t == 0) { g_kmax[row] = rm; g_ksum[row] = red[0]; }
}

// ---------------- ctx partials ----------------
__global__ void ctx_k() {
    int bh = blockIdx.y;
    int b = bh >> 2, head = bh & 3;
    int c0 = head * DH;
    int nbase = blockIdx.x * 512;
    int t = threadIdx.x;
    int d = t >> 4, e = t & 15;
    __shared__ float sk[16][65], sv[16][65];
    float acc = 0.f;
    for (int tile = 0; tile < 8; tile++) {
        int nb = nbase + tile*64;
        #pragma unroll
        for (int i = 0; i < 4; i++) {
            int idx = t + i*256;
            int dd = idx >> 6, j = idx & 63;
            int row = b*CC + c0 + dd;
            sk[dd][j] = __expf(g_ks[row*HWP + nb + j] - __ldg(&g_kmax[row]));
            sv[dd][j] = g_vs[row*HWP + nb + j];
        }
        __syncthreads();
        #pragma unroll
        for (int j = 0; j < 64; j++) acc += sk[d][j] * sv[e][j];
        __syncthreads();
    }
    g_ctxp[(blockIdx.x*16 + bh)*256 + t] = acc;
}

__global__ void ctx_red() {
    int bh = blockIdx.x;
    int t = threadIdx.x;
    float s = 0.f;
    #pragma unroll
    for (int ch = 0; ch < 64; ch++) s += g_ctxp[(ch*16 + bh)*256 + t];
    g_ctx[bh*256 + t] = s;
}

// ---------------- att = (ctx/ksum)^T * softmax_d(q) ----------------
__global__ void att_k() {
    int bh = blockIdx.y;
    int b = bh >> 2, head = bh & 3;
    int c0 = head * DH;
    int t = threadIdx.x;
    __shared__ float sc[16][17];
    { int d = t >> 4, e = t & 15;
      sc[d][e] = g_ctx[bh*256 + t] / g_ksum[b*CC + c0 + d]; }
    __syncthreads();
    int pid = blockIdx.x * 256 + t;
    float qv[16];
    float mx = -1e30f;
    #pragma unroll
    for (int d = 0; d < DH; d++) { qv[d] = g_qs[(b*CC + c0 + d)*HWP + pid]; mx = fmaxf(mx, qv[d]); }
    float s = 0.f;
    #pragma unroll
    for (int d = 0; d < DH; d++) { qv[d] = __expf(qv[d] - mx); s += qv[d]; }
    float inv = 1.f / s;
    #pragma unroll
    for (int d = 0; d < DH; d++) qv[d] *= inv;
    #pragma unroll
    for (int e = 0; e < DH; e++) {
        float a = 0.f;
        #pragma unroll
        for (int d = 0; d < DH; d++) a = fmaf(sc[d][e], qv[d], a);
        g_att[(b*CC + c0 + e)*HWP + pid] = a;
    }
}

// ---------------- parity-aware conv5x5 C->2C (bf16 tensor) ----------------
__global__ __launch_bounds__(512, 1) void conv5t(const float* __restrict__ rb) {
    extern __shared__ unsigned smem[];
    unsigned* swh = smem + SWH_U;
    unsigned* swl = smem + SWL_U;
    unsigned* sih = smem + SIH_U;
    unsigned* sil = smem + SIL_U;
    int bid = blockIdx.x;
    int p = bid & 1, h = (bid >> 1) & 255, b = bid >> 9;
    int t = threadIdx.x, lane = t & 31, warp = t >> 5;
    int mbase = (warp & 3) * 32, nbase = (warp >> 2) * 32;
    int wstart = p ^ (h & 1);
    const float* attb = g_att + b*CC*HWP;
    float acc[2][4][4] = {};
    for (int dy = 0; dy < 5; dy++) {
        int hr = h + dy - 2;
        if (hr < 0 || hr >= HH) continue;
        int dx0 = p ^ (dy & 1);
        int wpb0 = (wstart + dx0 - 2) >> 1;
        __syncthreads();                       // prior tap done reading s_in
        #pragma unroll
        for (int i = 0; i < 9; i++) {
            int idx = t + i*512;
            if (idx < 4160) {
                int kc = idx / 130, px = idx - kc*130;
                int wp = wpb0 + px;
                float v0 = 0.f, v1 = 0.f;
                if (wp >= 0 && wp < WP) {
                    v0 = attb[(2*kc  )*HWP + hr*WP + wp];
                    v1 = attb[(2*kc+1)*HWP + hr*WP + wp];
                }
                float h0 = __bfloat162float(__float2bfloat16_rn(v0));
                float h1 = __bfloat162float(__float2bfloat16_rn(v1));
                sih[kc*B_LD + px] = pack2(h0, h1);
                sil[kc*B_LD + px] = pack2(v0 - h0, v1 - h1);
            }
        }
        for (int dx = dx0; dx < 5; dx += 2) {
            int tap = dy*5 + dx;
            __syncthreads();                   // prior gemm done reading s_w
            #pragma unroll
            for (int i = 0; i < 8; i++) {
                int idx = t + i*512;
                int co = idx >> 5, kc = idx & 31;
                swh[co*A_LD + kc] = g_wrhu[tap*4096 + idx];
                swl[co*A_LD + kc] = g_wrlu[tap*4096 + idx];
            }
            __syncthreads();
            mma_chunk(swh, swl, sih, sil, lane, mbase, nbase, (dx - dx0) >> 1, acc);
        }
    }
    int r = lane >> 2, col = lane & 3;
    #pragma unroll
    for (int mt = 0; mt < 2; mt++) {
        #pragma unroll
        for (int nt = 0; nt < 4; nt++) {
            int co0 = mbase + mt*16 + r;
            int px0 = nbase + nt*8 + col*2;
            int wc0 = wstart + 2*px0;
            float bv0 = __ldg(rb + co0), bv8 = __ldg(rb + co0 + 8);
            float* r0p = g_attn + ((size_t)(b*C2 + co0)*HH + h)*WWF;
            float* r8p = r0p + (size_t)8*HH*WWF;
            r0p[wc0]     = acc[mt][nt][0] + bv0;
            r0p[wc0 + 2] = acc[mt][nt][1] + bv0;
            r8p[wc0]     = acc[mt][nt][2] + bv8;
            r8p[wc0 + 2] = acc[mt][nt][3] + bv8;
        }
    }
}

// ---------------- m1: 1x1 2C->4C + gelu (bf16 tensor) ----------------
__global__ __launch_bounds__(512, 1) void pw_m1t(const float* __restrict__ bias) {
    extern __shared__ unsigned smem[];
    unsigned* swh = smem + SWH_U;
    unsigned* swl = smem + SWL_U;
    unsigned* sih = smem + SIH_U;
    unsigned* sil = smem + SIL_U;
    int t = threadIdx.x, lane = t & 31, warp = t >> 5;
    int mbase = (warp & 3) * 32, nbase = (warp >> 2) * 32;
    int n0 = blockIdx.x * 128;
    int cohalf = blockIdx.y;
    int b = n0 >> 16, rem0 = n0 & 65535;
    float acc[2][4][4] = {};
    for (int cc = 0; cc < 2; cc++) {
        int ci0 = cc * 64;
        if (cc) __syncthreads();
        #pragma unroll
        for (int i = 0; i < 8; i++) {
            int idx = t + i*512;
            int co = idx >> 5, kc = idx & 31;
            swh[co*A_LD + kc] = g_m1hu[(cohalf*128 + co)*64 + cc*32 + kc];
            swl[co*A_LD + kc] = g_m1lu[(cohalf*128 + co)*64 + cc*32 + kc];
        }
        #pragma unroll
        for (int i = 0; i < 8; i++) {
            int idx = t + i*512;
            int kc = idx >> 7, px = idx & 127;
            float v0 = g_attn[(size_t)(b*C2 + ci0 + 2*kc  )*HW + rem0 + px];
            float v1 = g_attn[(size_t)(b*C2 + ci0 + 2*kc+1)*HW + rem0 + px];
            float h0 = __bfloat162float(__float2bfloat16_rn(v0));
            float h1 = __bfloat162float(__float2bfloat16_rn(v1));
            sih[kc*B_LD + px] = pack2(h0, h1);
            sil[kc*B_LD + px] = pack2(v0 - h0, v1 - h1);
        }
        __syncthreads();
        mma_chunk(swh, swl, sih, sil, lane, mbase, nbase, 0, acc);
    }
    int r = lane >> 2, col = lane & 3;
    #pragma unroll
    for (int mt = 0; mt < 2; mt++) {
        #pragma unroll
        for (int nt = 0; nt < 4; nt++) {
            int co = cohalf*128 + mbase + mt*16 + r;
            int px = nbase + nt*8 + col*2;
            float bv0 = __ldg(bias + co), bv8 = __ldg(bias + co + 8);
            float2 o0 = make_float2(gelu_exact(acc[mt][nt][0] + bv0),
                                    gelu_exact(acc[mt][nt][1] + bv0));
            float2 o8 = make_float2(gelu_exact(acc[mt][nt][2] + bv8),
                                    gelu_exact(acc[mt][nt][3] + bv8));
            *reinterpret_cast<float2*>(&g_m1[(size_t)(b*C4 + co)*HW + rem0 + px]) = o0;
            *reinterpret_cast<float2*>(&g_m1[(size_t)(b*C4 + co + 8)*HW + rem0 + px]) = o8;
        }
    }
}

// ---------------- m2: depthwise 3x3 on 4C + gelu ----------------
__global__ void dw_m2(const float* __restrict__ w, const float* __restrict__ bias) {
    int idx = blockIdx.x * 256 + threadIdx.x;
    int wq = idx & 255;
    int h  = (idx >> 8) & 255;
    int c  = (idx >> 16) & 255;
    int b  = idx >> 24;
    const float* ip = g_m1 + ((size_t)(b*C4 + c) << 16);
    float wg[9];
    #pragma unroll
    for (int k = 0; k < 9; k++) wg[k] = __ldg(w + c*9 + k);
    float acc = __ldg(bias + c);
    #pragma unroll
    for (int ky = 0; ky < 3; ky++) {
        int hh = h + ky - 1;
        if (hh < 0 || hh >= HH) continue;
        #pragma unroll
        for (int kx = 0; kx < 3; kx++) {
            int ww = wq + kx - 1;
            if (ww < 0 || ww >= WWF) continue;
            acc += wg[ky*3+kx] * __ldg(ip + hh*WWF + ww);
        }
    }
    g_m2[idx] = gelu_exact(acc);
}

// ---------------- m3: 1x1 4C->2C + residual (bf16 tensor), writes d_out ----------------
__global__ __launch_bounds__(512, 1) void pw_m3t(const float* __restrict__ bias,
                                                 float* __restrict__ out) {
    extern __shared__ unsigned smem[];
    unsigned* swh = smem + SWH_U;
    unsigned* swl = smem + SWL_U;
    unsigned* sih = smem + SIH_U;
    unsigned* sil = smem + SIL_U;
    int t = threadIdx.x, lane = t & 31, warp = t >> 5;
    int mbase = (warp & 3) * 32, nbase = (warp >> 2) * 32;
    int n0 = blockIdx.x * 128;
    int b = n0 >> 16, rem0 = n0 & 65535;
    float acc[2][4][4] = {};
    for (int cc = 0; cc < 4; cc++) {
        int ci0 = cc * 64;
        if (cc) __syncthreads();
        #pragma unroll
        for (int i = 0; i < 8; i++) {
            int idx = t + i*512;
            int co = idx >> 5, kc = idx & 31;
            swh[co*A_LD + kc] = g_m3hu[co*128 + cc*32 + kc];
            swl[co*A_LD + kc] = g_m3lu[co*128 + cc*32 + kc];
        }
        #pragma unroll
        for (int i = 0; i < 8; i++) {
            int idx = t + i*512;
            int kc = idx >> 7, px = idx & 127;
            float v0 = g_m2[(size_t)(b*C4 + ci0 + 2*kc  )*HW + rem0 + px];
            float v1 = g_m2[(size_t)(b*C4 + ci0 + 2*kc+1)*HW + rem0 + px];
            float h0 = __bfloat162float(__float2bfloat16_rn(v0));
            float h1 = __bfloat162float(__float2bfloat16_rn(v1));
            sih[kc*B_LD + px] = pack2(h0, h1);
            sil[kc*B_LD + px] = pack2(v0 - h0, v1 - h1);
        }
        __syncthreads();
        mma_chunk(swh, swl, sih, sil, lane, mbase, nbase, 0, acc);
    }
    int r = lane >> 2, col = lane & 3;
    #pragma unroll
    for (int mt = 0; mt < 2; mt++) {
        #pragma unroll
        for (int nt = 0; nt < 4; nt++) {
            int co = mbase + mt*16 + r;
            int px = nbase + nt*8 + col*2;
            float bv0 = __ldg(bias + co), bv8 = __ldg(bias + co + 8);
            size_t off0 = (size_t)(b*C2 + co)*HW + rem0 + px;
            size_t off8 = (size_t)(b*C2 + co + 8)*HW + rem0 + px;
            float2 r0 = *reinterpret_cast<const float2*>(&g_attn[off0]);
            float2 r8 = *reinterpret_cast<const float2*>(&g_attn[off8]);
            float2 o0 = make_float2(acc[mt][nt][0] + bv0 + r0.x,
                                    acc[mt][nt][1] + bv0 + r0.y);
            float2 o8 = make_float2(acc[mt][nt][2] + bv8 + r8.x,
                                    acc[mt][nt][3] + bv8 + r8.y);
            *reinterpret_cast<float2*>(&out[off0]) = o0;
            *reinterpret_cast<float2*>(&out[off8]) = o8;
        }
    }
}

// ---------------- launch ----------------
extern "C" void kernel_launch(void* const* d_in, const int* in_sizes, int n_in,
                              void* d_out, int out_size) {
    const float* x1   = (const float*)d_in[0];
    const float* x2   = (const float*)d_in[1];
    const float* q1_w = (const float*)d_in[2];  const float* q1_b = (const float*)d_in[3];
    const float* q2_w = (const float*)d_in[4];  const float* q2_b = (const float*)d_in[5];
    const float* k1_w = (const float*)d_in[6];  const float* k1_b = (const float*)d_in[7];
    const float* k2_w = (const float*)d_in[8];  const float* k2_b = (const float*)d_in[9];
    const float* v1_w = (const float*)d_in[10]; const float* v1_b = (const float*)d_in[11];
    const float* v2_w = (const float*)d_in[12]; const float* v2_b = (const float*)d_in[13];
    const float* r_w  = (const float*)d_in[14]; const float* r_b  = (const float*)d_in[15];
    const float* m1_w = (const float*)d_in[16]; const float* m1_b = (const float*)d_in[17];
    const float* m2_w = (const float*)d_in[18]; const float* m2_b = (const float*)d_in[19];
    const float* m3_w = (const float*)d_in[20]; const float* m3_b = (const float*)d_in[21];
    float* out = (float*)d_out;

    cudaFuncSetAttribute(conv5t, cudaFuncAttributeMaxDynamicSharedMemorySize, SMEM_BYTES);
    cudaFuncSetAttribute(pw_m1t, cudaFuncAttributeMaxDynamicSharedMemorySize, SMEM_BYTES);
    cudaFuncSetAttribute(pw_m3t, cudaFuncAttributeMaxDynamicSharedMemorySize, SMEM_BYTES);

    prep_w<<<576, 256>>>(q1_w, k1_w, v1_w, r_w, m1_w, m3_w);

    // round-2 exact q/k/v pipeline (known good)
    pw64<<<4096, 256>>>(x1, 0, q1_b, 2);
    dwsq<<<32768, 256>>>(q2_w, q2_b, 0, 0);
    pw64<<<4096, 256>>>(x1, 1, k1_b, 1);
    dwsq<<<32768, 256>>>(k2_w, k2_b, 1, 1);
    pw64<<<4096, 256>>>(x2, 2, v1_b, 0);
    dwsq<<<32768, 256>>>(v2_w, v2_b, 2, 1);

    kstat<<<256, 256>>>();
    ctx_k<<<dim3(64, 16), 256>>>();
    ctx_red<<<16, 256>>>();
    att_k<<<dim3(128, 16), 256>>>();

    conv5t<<<2048, 512, SMEM_BYTES>>>(r_b);

    pw_m1t<<<dim3(2048, 2), 512, SMEM_BYTES>>>(m1_b);
    dw_m2<<<262144, 256>>>(m2_w, m2_b);
    pw_m3t<<<2048, 512, SMEM_BYTES>>>(m3_b, out);
}